// round 16
// baseline (speedup 1.0000x reference)
#include <cuda_runtime.h>
#include <cuda_fp16.h>
#include <cstddef>
#include <cstdint>

// ---------------- problem constants ----------------
#define Bsz   32
#define CINc  16
#define Hh    32
#define Ww    128
#define Oc    128
#define NTOT  512          // 128 channels x 4 gates, n = ch*4 + gate
#define ASTR  168          // A half-stride (84 words; LDSM 8-row banks distinct)
#define BSTR  152          // B half-stride (76 words; LDSM 8-row banks distinct)
#define THREADS 512

// ---------------- shared memory layout (bytes) ----------------
// sA rows (per half h: base = h*64):
//   h*64 + 0..15   top buf0      h*64 + 16..31  top buf1
//   h*64 + 32..47  left buf0     h*64 + 48..63  left buf1
// (left rows carry h cols 0-127 and x cols 128-143)
#define OFF_B     0
#define SZ_B      (NTOT * BSTR * 2)            // 155648
#define OFF_A     (OFF_B + SZ_B)               // 155648
#define SZ_A      (128 * ASTR * 2)             // 43008
#define OFF_BIAS  (OFF_A + SZ_A)               // 198656
#define SZ_BIAS   (5 * Oc * 4)                 // 2560
#define SMEM_TOTAL (OFF_BIAS + SZ_BIAS)        // 201216

// transpose tile stride (halves); 69 words odd -> conflict-free strided reads
#define TTS 138

// ---------------- global scratch ----------------
// g_hbuf column (4096 halves): [half(2)][chBlk(16)][b(16)][8ch]
// g_cbuf column (4096 floats): [half(2)][j(2)][tidh(256)*4]
__device__ __align__(256) __half  g_hbuf[(size_t)128 * 128 * 32 * 128];
__device__ __align__(256) float   g_cbuf[(size_t)128 * 128 * 32 * 128];
__device__ unsigned               g_prog[128][2];

// ---------------- helpers ----------------
__device__ __forceinline__ float tnhf(float x) {
    float y;
    asm("tanh.approx.f32 %0, %1;" : "=f"(y) : "f"(x));
    return y;
}
__device__ __forceinline__ float sigf(float x) {
    return fmaf(tnhf(0.5f * x), 0.5f, 0.5f);
}
__device__ __forceinline__ unsigned ld_acq(const unsigned* p) {
    unsigned v;
    asm volatile("ld.acquire.gpu.global.b32 %0, [%1];" : "=r"(v) : "l"(p));
    return v;
}
__device__ __forceinline__ void st_rel(unsigned* p, unsigned v) {
    asm volatile("st.release.gpu.global.b32 [%0], %1;" :: "l"(p), "r"(v) : "memory");
}
__device__ __forceinline__ unsigned pack2h(float lo, float hi) {
    return (unsigned)__half_as_ushort(__float2half(lo))
         | ((unsigned)__half_as_ushort(__float2half(hi)) << 16);
}
__device__ __forceinline__ void hbar(int id) {
    asm volatile("bar.sync %0, 256;" :: "r"(id) : "memory");
}
__device__ __forceinline__ void mma16816(float* c, const unsigned* a, unsigned b0, unsigned b1) {
    asm volatile(
        "mma.sync.aligned.m16n8k16.row.col.f32.f16.f16.f32 "
        "{%0,%1,%2,%3}, {%4,%5,%6,%7}, {%8,%9}, {%0,%1,%2,%3};"
        : "+f"(c[0]), "+f"(c[1]), "+f"(c[2]), "+f"(c[3])
        : "r"(a[0]), "r"(a[1]), "r"(a[2]), "r"(a[3]), "r"(b0), "r"(b1));
}
__device__ __forceinline__ void ldsm_x4(unsigned* r, unsigned addr) {
    asm volatile(
        "ldmatrix.sync.aligned.m8n8.x4.shared.b16 {%0,%1,%2,%3}, [%4];"
        : "=r"(r[0]), "=r"(r[1]), "=r"(r[2]), "=r"(r[3]) : "r"(addr));
}

__global__ void init_progress_kernel() {
    if (threadIdx.x < 256) (&g_prog[0][0])[threadIdx.x] = 0u;
}

// ---------------- main persistent kernel: one CTA per (direction, row),
// two independent batch-half wavefronts per CTA ----------------
__global__ void __launch_bounds__(THREADS, 1) mdlstm_kernel(
    const float* __restrict__ x,
    const float* __restrict__ w_ii, const float* __restrict__ w_hi, const float* __restrict__ b_i,
    const float* __restrict__ w_if, const float* __restrict__ w_hf, const float* __restrict__ b_f,
    const float* __restrict__ w_ig, const float* __restrict__ w_hg, const float* __restrict__ b_g,
    const float* __restrict__ w_io, const float* __restrict__ w_ho, const float* __restrict__ b_o,
    const float* __restrict__ wsum, const float* __restrict__ biasv,
    float* __restrict__ out)
{
    extern __shared__ char smem[];
    __half* sB    = reinterpret_cast<__half*>(smem + OFF_B);
    __half* sA    = reinterpret_cast<__half*>(smem + OFF_A);
    float*  sBias = reinterpret_cast<float*>(smem + OFF_BIAS);

    const int tid  = threadIdx.x;
    const int lane = tid & 31;
    const int wid  = tid >> 5;          // 0..15
    const int half = wid >> 3;          // 0 / 1  (batch half)
    const int hwid = wid & 7;           // warp within half
    const int tidh = tid & 255;         // thread within half
    const int bid  = blockIdx.x;
    const int d    = bid >> 5;
    const int r    = bid & 31;
    const bool fx  = (d & 1) != 0;
    const bool fy  = (d & 2) != 0;
    const int  ph  = fy ? (Hh - 1 - r) : r;

    // ---- stage weights: sB[n][k], n = ch*4 + gate ----
    {
        const float* whArr[4] = {w_hi, w_hf, w_hg, w_ho};
        const float* wiArr[4] = {w_ii, w_if, w_ig, w_io};
        for (int gate = 0; gate < 4; ++gate) {
            const float* wh = whArr[gate] + (size_t)d * Oc * Oc;
            for (int idx = tid; idx < Oc * Oc; idx += THREADS) {
                int ch = idx >> 7, k = idx & 127;
                sB[(ch * 4 + gate) * BSTR + k] = __float2half(wh[idx]);
            }
            const float* wi = wiArr[gate] + (size_t)d * Oc * CINc;
            for (int idx = tid; idx < Oc * CINc; idx += THREADS) {
                int ch = idx >> 4, k = idx & 15;
                sB[(ch * 4 + gate) * BSTR + 128 + k] = __float2half(wi[idx]);
            }
        }
        const float* bArr[4] = {b_i, b_f, b_g, b_o};
        sBias[tid] = bArr[tid >> 7][(size_t)d * Oc + (tid & 127)];
        if (tid < 128) sBias[512 + tid] = biasv[(size_t)d * Oc + tid];
        // zero left buf0 h cols (read at w=0), both halves
        for (int idx = tid; idx < 2 * 16 * 128; idx += THREADS) {
            int h_ = idx >> 11, b = (idx >> 7) & 15, c = idx & 127;
            sA[(h_ * 64 + 32 + b) * ASTR + c] = __float2half(0.f);
        }
        if (r == 0) {   // h_top = 0 forever: zero both top buffers, both halves
            for (int idx = tid; idx < 2 * 32 * 128; idx += THREADS) {
                int h_ = idx >> 12, b = (idx >> 7) & 31, c = idx & 127;
                sA[(h_ * 64 + b) * ASTR + c] = __float2half(0.f);
            }
        }
    }
    const float ws0 = wsum[d * 2 + 0];
    const float ws1 = wsum[d * 2 + 1];

    const int g = lane >> 2, t = lane & 3;
    const bool oddt = (t & 1) != 0;
    const bool hiT  = (t >> 1) != 0;     // owns odd channel offsets

    // per-thread epilogue ownership: ch = chB + nt*2 (nt 0..7), bb = batch within half
    const int chB = (hwid << 4) + (t >> 1);
    const int bb  = g + (oddt ? 8 : 0);               // 0..15
    const int n0  = hwid << 6;                        // warp's 64 n-cols
    const int sx_b = tidh >> 4, sx_ci = tidh & 15;    // staging map (b, ci/colblk)
    const int barid = 1 + half;

    // ldmatrix per-lane address roles (m16 tiles)
    const unsigned sAu = (unsigned)__cvta_generic_to_shared(sA);
    const unsigned sBu = (unsigned)__cvta_generic_to_shared(sB);
    const int aro  = (lane & 7) + ((lane >> 3) & 1) * 8;   // row within 16
    const int ako  = (lane >> 4) * 8;                      // k-half offset
    const unsigned aAtop0  = sAu + (unsigned)(((half * 64 + aro) * ASTR + ako) * 2);        // +tb*16 rows
    const unsigned aAleft0 = sAu + (unsigned)(((half * 64 + 32 + aro) * ASTR + ako) * 2);   // +cur*16 rows
    const unsigned aBU     = sBu + (unsigned)(((n0 + ((lane >> 4) & 1) * 8 + (lane & 7)) * BSTR
                                               + ((lane >> 3) & 1) * 8) * 2);

    float cleft[8];
#pragma unroll
    for (int nt = 0; nt < 8; ++nt) cleft[nt] = 0.f;

    unsigned avail = 0;
    // x: tid == (batch*CINc + ci) exactly (CINc=16, batch = half*16 + sx_b)
    const float* xrow = x + (size_t)tid * (Hh * Ww) + (size_t)ph * Ww;
    const int xm = fx ? 3 : 0;

    // prologue: stage x(0) into left buf0 x-cols
    float4 xq = *reinterpret_cast<const float4*>(xrow + (fx ? 124 : 0));
    {
        const int e = 0 ^ xm;
        float s01 = (e & 1) ? xq.y : xq.x;
        float s23 = (e & 1) ? xq.w : xq.z;
        sA[(half * 64 + 32 + sx_b) * ASTR + 128 + sx_ci] = __float2half((e & 2) ? s23 : s01);
    }
    __syncthreads();   // weights + zeros visible to both halves

#pragma unroll 1
    for (int w = 0; w < Ww; ++w) {
        const int cur = w & 1, nxt = cur ^ 1, tb = w & 1;
        const size_t rowoff = ((size_t)bid * Ww + w) * (Bsz * Oc);
        const size_t topoff = rowoff - (size_t)Ww * (Bsz * Oc);
        const size_t hoff   = (size_t)half * 2048;

        // ---- head: poll this half's producer flag, LDG h_top/c_top, stage h_top ----
        float ctop_[8];
        if (r > 0) {
            if (avail <= (unsigned)w) {
                avail = ld_acq(&g_prog[bid - 1][half]);
                while (avail <= (unsigned)w) { __nanosleep(32); avail = ld_acq(&g_prog[bid - 1][half]); }
            }
            // blocked: [half][chBlk=sx_ci][b=sx_b][8]
            uint4 htop_v = *reinterpret_cast<const uint4*>(
                g_hbuf + topoff + hoff + (size_t)sx_ci * 128 + (size_t)sx_b * 8);
            float4 q0 = *reinterpret_cast<const float4*>(g_cbuf + topoff + hoff + (tidh << 2));
            float4 q1 = *reinterpret_cast<const float4*>(g_cbuf + topoff + hoff + 1024 + (tidh << 2));
            ctop_[0] = q0.x; ctop_[1] = q0.y; ctop_[2] = q0.z; ctop_[3] = q0.w;
            ctop_[4] = q1.x; ctop_[5] = q1.y; ctop_[6] = q1.z; ctop_[7] = q1.w;
            // double-buffered top staging: readers of top[tb] were step w-2
            *reinterpret_cast<uint4*>(
                sA + (half * 64 + tb * 16 + sx_b) * ASTR + sx_ci * 8) = htop_v;
        } else {
#pragma unroll
            for (int nt = 0; nt < 8; ++nt) ctop_[nt] = 0.f;
        }
        hbar(barid);   // S_A (per half)

        const unsigned aAleftU = aAleft0 + (unsigned)(cur * (16 * ASTR * 2));
        const unsigned aAtopU  = aAtop0  + (unsigned)(tb  * (16 * ASTR * 2));

        // ================= pass L: LEFT branch (left[cur]; k=8 = x cols) =================
        float htp[8];
        {
            float acc[8][4];
#pragma unroll
            for (int nt = 0; nt < 8; ++nt)
#pragma unroll
                for (int q = 0; q < 4; ++q) acc[nt][q] = 0.f;

#pragma unroll
            for (int k = 0; k < 9; ++k) {
                unsigned a0[4];
                ldsm_x4(a0, aAleftU + (unsigned)(k * 32));
#pragma unroll
                for (int j = 0; j < 4; ++j) {
                    unsigned bq[4];
                    ldsm_x4(bq, aBU + (unsigned)(j * 16 * BSTR * 2 + k * 32));
                    mma16816(acc[2 * j],     a0, bq[0], bq[1]);
                    mma16816(acc[2 * j + 1], a0, bq[2], bq[3]);
                }
            }
#pragma unroll
            for (int nt = 0; nt < 8; ++nt) {
                float* c1 = acc[nt];
                float rA = __shfl_xor_sync(0xffffffffu, oddt ? c1[0] : c1[2], 1);
                float rB = __shfl_xor_sync(0xffffffffu, oddt ? c1[1] : c1[3], 1);
                float pi, pf, pg, po;
                if (!oddt) { pi = c1[0]; pf = c1[1]; pg = rA;    po = rB; }
                else       { pi = rA;    pf = rB;    pg = c1[2]; po = c1[3]; }
                const int ch = chB + nt * 2;
                const float i1 = sigf(pi + sBias[ch]);
                const float f1 = sigf(pf + sBias[128 + ch]);
                const float g1 = tnhf(pg + sBias[256 + ch]);
                const float o1 = sigf(po + sBias[384 + ch]);
                const float cn1 = f1 * cleft[nt] + i1 * g1;
                htp[nt]   = o1 * tnhf(cn1);
                cleft[nt] = cn1;                 // cn1 carrier
            }
        }

        // ================= pass T: TOP branch (top[tb]; k=8 from left[cur] x cols) ========
        float ht_s[8];
        {
            float acc[8][4];
#pragma unroll
            for (int nt = 0; nt < 8; ++nt)
#pragma unroll
                for (int q = 0; q < 4; ++q) acc[nt][q] = 0.f;

#pragma unroll
            for (int k = 0; k < 9; ++k) {
                const unsigned ab = (k < 8) ? (aAtopU + (unsigned)(k * 32))
                                            : (aAleftU + (unsigned)(8 * 32));
                unsigned a0[4];
                ldsm_x4(a0, ab);
#pragma unroll
                for (int j = 0; j < 4; ++j) {
                    unsigned bq[4];
                    ldsm_x4(bq, aBU + (unsigned)(j * 16 * BSTR * 2 + k * 32));
                    mma16816(acc[2 * j],     a0, bq[0], bq[1]);
                    mma16816(acc[2 * j + 1], a0, bq[2], bq[3]);
                }
            }
#pragma unroll
            for (int nt = 0; nt < 8; ++nt) {
                float* c0 = acc[nt];
                float rA = __shfl_xor_sync(0xffffffffu, oddt ? c0[0] : c0[2], 1);
                float rB = __shfl_xor_sync(0xffffffffu, oddt ? c0[1] : c0[3], 1);
                float pi, pf, pg, po;
                if (!oddt) { pi = c0[0]; pf = c0[1]; pg = rA;    po = rB; }
                else       { pi = rA;    pf = rB;    pg = c0[2]; po = c0[3]; }
                const int ch = chB + nt * 2;
                const float i0 = sigf(pi + sBias[ch]);
                const float f0 = sigf(pf + sBias[128 + ch]);
                const float g0 = tnhf(pg + sBias[256 + ch]);
                const float o0 = sigf(po + sBias[384 + ch]);
                const float cn0 = f0 * ctop_[nt] + i0 * g0;
                const float h0  = o0 * tnhf(cn0);

                const float bv = sBias[512 + ch];
                const float ct = fmaf(ws0, cn0, fmaf(ws1, cleft[nt], bv));
                const float ht = fmaf(ws0, h0,  fmaf(ws1, htp[nt],  bv));

                cleft[nt] = ct;
                ht_s[nt]  = ht;
                sA[(half * 64 + 32 + nxt * 16 + bb) * ASTR + ch] = __float2half(ht);  // h_left
            }
        }

        // ---- publish h(w): lane^2 parity exchange -> one coalesced uint4 per thread ----
        {
            float rx[4];
#pragma unroll
            for (int j = 0; j < 4; ++j)
                rx[j] = __shfl_xor_sync(0xffffffffu, hiT ? ht_s[j] : ht_s[j + 4], 2);
            uint4 pk;
            if (!hiT) {   // ch block chB16 + 0..7: even = own nt0-3, odd = partner nt0-3
                pk.x = pack2h(ht_s[0], rx[0]);
                pk.y = pack2h(ht_s[1], rx[1]);
                pk.z = pack2h(ht_s[2], rx[2]);
                pk.w = pack2h(ht_s[3], rx[3]);
            } else {      // ch block + 8..15: even = partner nt4-7, odd = own nt4-7
                pk.x = pack2h(rx[0], ht_s[4]);
                pk.y = pack2h(rx[1], ht_s[5]);
                pk.z = pack2h(rx[2], ht_s[6]);
                pk.w = pack2h(rx[3], ht_s[7]);
            }
            const int blk = hwid * 2 + (hiT ? 1 : 0);
            *reinterpret_cast<uint4*>(
                g_hbuf + rowoff + hoff + (size_t)blk * 128 + (size_t)bb * 8) = pk;
        }

        // ---- publish c (thread-packed per half, coalesced) ----
        *reinterpret_cast<float4*>(g_cbuf + rowoff + hoff + (tidh << 2)) =
            make_float4(cleft[0], cleft[1], cleft[2], cleft[3]);
        *reinterpret_cast<float4*>(g_cbuf + rowoff + hoff + 1024 + (tidh << 2)) =
            make_float4(cleft[4], cleft[5], cleft[6], cleft[7]);

        // ---- stage x(w+1) into left[nxt] x-cols (disjoint from h cols) ----
        if (w + 1 < Ww) {
            const int e = w + 1;
            if ((e & 3) == 0)
                xq = *reinterpret_cast<const float4*>(xrow + (fx ? (124 - e) : e));
            const int ei = (e & 3) ^ xm;
            float s01 = (ei & 1) ? xq.y : xq.x;
            float s23 = (ei & 1) ? xq.w : xq.z;
            sA[(half * 64 + 32 + nxt * 16 + sx_b) * ASTR + 128 + sx_ci] =
                __float2half((ei & 2) ? s23 : s01);
        }

        hbar(barid);   // S_rel (per half): all this half's stores done
        if (tidh == 0) st_rel(&g_prog[bid][half], (unsigned)(w + 1));
    }

    // ---- output epilogue: transpose f16 row history -> coalesced fp32 stores ----
    // g_hbuf column: [half][chBlk16][b16][8]; out[d][ch][b][ph][pw], w = fx ? 127-pw : pw
    __half* tile = reinterpret_cast<__half*>(smem);   // reuse sB region
    float* outp = out + (size_t)d * Oc * Bsz * Hh * Ww;
    __syncthreads();
#pragma unroll 1
    for (int b = 0; b < Bsz; ++b) {
        const size_t boff = (size_t)(b >> 4) * 2048 + (size_t)(b & 15) * 8;
#pragma unroll 1
        for (int idx = tid; idx < 128 * 64; idx += THREADS) {   // u32 units: 128 w x 64 ch-pairs
            int wq = idx >> 6, s = idx & 63;
            unsigned v = *reinterpret_cast<const unsigned*>(
                g_hbuf + ((size_t)bid * Ww + wq) * (Bsz * Oc)
                       + boff + (size_t)(s >> 2) * 128 + (s & 3) * 2);
            *reinterpret_cast<unsigned*>(tile + wq * TTS + s * 2) = v;
        }
        __syncthreads();
#pragma unroll 1
        for (int idx = tid; idx < 128 * 128; idx += THREADS) {
            int ch = idx >> 7, pw = idx & 127;
            int ww = fx ? (127 - pw) : pw;
            outp[(((size_t)ch * Bsz + b) * Hh + ph) * Ww + pw] =
                __half2float(tile[ww * TTS + ch]);
        }
        __syncthreads();
    }
}

// ---------------- launch ----------------
extern "C" void kernel_launch(void* const* d_in, const int* in_sizes, int n_in,
                              void* d_out, int out_size)
{
    const float* x     = (const float*)d_in[0];
    const float* w_ii  = (const float*)d_in[1];
    const float* w_hi  = (const float*)d_in[2];
    const float* b_i   = (const float*)d_in[3];
    const float* w_if  = (const float*)d_in[4];
    const float* w_hf  = (const float*)d_in[5];
    const float* b_f   = (const float*)d_in[6];
    const float* w_ig  = (const float*)d_in[7];
    const float* w_hg  = (const float*)d_in[8];
    const float* b_g   = (const float*)d_in[9];
    const float* w_io  = (const float*)d_in[10];
    const float* w_ho  = (const float*)d_in[11];
    const float* b_o   = (const float*)d_in[12];
    const float* wsum  = (const float*)d_in[13];
    const float* biasv = (const float*)d_in[14];
    float* out = (float*)d_out;

    cudaFuncSetAttribute(mdlstm_kernel,
                         cudaFuncAttributeMaxDynamicSharedMemorySize, SMEM_TOTAL);

    init_progress_kernel<<<1, 256>>>();
    mdlstm_kernel<<<128, THREADS, SMEM_TOTAL>>>(
        x, w_ii, w_hi, b_i, w_if, w_hf, b_f, w_ig, w_hg, b_g,
        w_io, w_ho, b_o, wsum, biasv, out);
}